// round 4
// baseline (speedup 1.0000x reference)
#include <cuda_runtime.h>
#include <cuda_bf16.h>
#include <math.h>
#include <stdint.h>

#define NN 4096
#define HH 64

// ---------------------------------------------------------------- scratch
__device__ float d_wiu[NN * HH];
__device__ float d_h[NN * HH];
__device__ float d_part[4 * NN * HH];                    // split-K partials
__device__ __nv_bfloat16 d_Lhi[(size_t)NN * NN];
__device__ __nv_bfloat16 d_Llo[(size_t)NN * NN];
__device__ __nv_bfloat16 d_gThi[HH * NN];                // g^T [64][4096]
__device__ __nv_bfloat16 d_gTlo[HH * NN];

// ---------------------------------------------------------------- PTX utils
__device__ __forceinline__ uint32_t smem_u32(const void* p) {
    uint32_t a;
    asm("{ .reg .u64 t; cvta.to.shared.u64 t, %1; cvt.u32.u64 %0, t; }"
        : "=r"(a) : "l"(p));
    return a;
}
#define SWZ128(o) ((o) ^ (((o) >> 3) & 0x70))

__device__ __forceinline__ void cp16(uint32_t s, const void* g) {
    asm volatile("cp.async.cg.shared.global [%0], [%1], 16;" :: "r"(s), "l"(g));
}
#define CP_COMMIT() asm volatile("cp.async.commit_group;" ::: "memory")
#define CP_WAIT3()  asm volatile("cp.async.wait_group 3;" ::: "memory")

__device__ __forceinline__ void ldsm_x4(uint32_t* r, uint32_t addr) {
    asm volatile("ldmatrix.sync.aligned.m8n8.x4.shared.b16 {%0,%1,%2,%3}, [%4];"
        : "=r"(r[0]), "=r"(r[1]), "=r"(r[2]), "=r"(r[3]) : "r"(addr));
}

__device__ __forceinline__ void mma16816(float* c, const uint32_t* a,
                                         uint32_t b0, uint32_t b1) {
    asm volatile(
        "mma.sync.aligned.m16n8k16.row.col.f32.bf16.bf16.f32 "
        "{%0,%1,%2,%3}, {%4,%5,%6,%7}, {%8,%9}, {%0,%1,%2,%3};"
        : "+f"(c[0]), "+f"(c[1]), "+f"(c[2]), "+f"(c[3])
        : "r"(a[0]), "r"(a[1]), "r"(a[2]), "r"(a[3]), "r"(b0), "r"(b1));
}

// ---------------------------------------------------------------- L split (once)
__global__ __launch_bounds__(256, 4) void lsplit_k(
    const float* __restrict__ L,
    __nv_bfloat16* __restrict__ Lhi, __nv_bfloat16* __restrict__ Llo)
{
    size_t i = ((size_t)blockIdx.x * 256 + threadIdx.x) * 4;
    float4 v = *(const float4*)(L + i);
    __nv_bfloat16 h0 = __float2bfloat16(v.x);
    __nv_bfloat16 h1 = __float2bfloat16(v.y);
    __nv_bfloat16 h2 = __float2bfloat16(v.z);
    __nv_bfloat16 h3 = __float2bfloat16(v.w);
    __nv_bfloat16 l0 = __float2bfloat16(v.x - __bfloat162float(h0));
    __nv_bfloat16 l1 = __float2bfloat16(v.y - __bfloat162float(h1));
    __nv_bfloat16 l2 = __float2bfloat16(v.z - __bfloat162float(h2));
    __nv_bfloat16 l3 = __float2bfloat16(v.w - __bfloat162float(h3));
    __nv_bfloat162 hp0 = __halves2bfloat162(h0, h1), hp1 = __halves2bfloat162(h2, h3);
    __nv_bfloat162 lp0 = __halves2bfloat162(l0, l1), lp1 = __halves2bfloat162(l2, l3);
    *(uint2*)(Lhi + i) = make_uint2(*(uint32_t*)&hp0, *(uint32_t*)&hp1);
    *(uint2*)(Llo + i) = make_uint2(*(uint32_t*)&lp0, *(uint32_t*)&lp1);
}

// ---------------------------------------------------------------- wiu small GEMM
__global__ __launch_bounds__(256, 1) void small_gemm_k(
    const float* __restrict__ A, const float* __restrict__ W,
    float* __restrict__ out)
{
    __shared__ float As[64][65];
    __shared__ float Ws[64][68];
    const int tid = threadIdx.x;
    const int base = blockIdx.x * (64 * 64);
    for (int i = tid; i < 4096; i += 256) {
        Ws[i & 63][i >> 6] = W[i];
        As[i >> 6][i & 63] = A[base + i];
    }
    __syncthreads();
    const int r = tid & 63, cg = tid >> 6;
    float acc[16];
#pragma unroll
    for (int j = 0; j < 16; ++j) acc[j] = 0.f;
#pragma unroll 8
    for (int k = 0; k < 64; ++k) {
        float a = As[r][k];
        const float* wr = &Ws[k][cg << 4];
        float4 b0 = *(const float4*)(wr + 0);
        float4 b1 = *(const float4*)(wr + 4);
        float4 b2 = *(const float4*)(wr + 8);
        float4 b3 = *(const float4*)(wr + 12);
        acc[0]  = fmaf(a, b0.x, acc[0]);  acc[1]  = fmaf(a, b0.y, acc[1]);
        acc[2]  = fmaf(a, b0.z, acc[2]);  acc[3]  = fmaf(a, b0.w, acc[3]);
        acc[4]  = fmaf(a, b1.x, acc[4]);  acc[5]  = fmaf(a, b1.y, acc[5]);
        acc[6]  = fmaf(a, b1.z, acc[6]);  acc[7]  = fmaf(a, b1.w, acc[7]);
        acc[8]  = fmaf(a, b2.x, acc[8]);  acc[9]  = fmaf(a, b2.y, acc[9]);
        acc[10] = fmaf(a, b2.z, acc[10]); acc[11] = fmaf(a, b2.w, acc[11]);
        acc[12] = fmaf(a, b3.x, acc[12]); acc[13] = fmaf(a, b3.y, acc[13]);
        acc[14] = fmaf(a, b3.z, acc[14]); acc[15] = fmaf(a, b3.w, acc[15]);
    }
    float* op = out + base + r * 64 + (cg << 4);
    *(float4*)(op + 0)  = make_float4(acc[0],  acc[1],  acc[2],  acc[3]);
    *(float4*)(op + 4)  = make_float4(acc[4],  acc[5],  acc[6],  acc[7]);
    *(float4*)(op + 8)  = make_float4(acc[8],  acc[9],  acc[10], acc[11]);
    *(float4*)(op + 12) = make_float4(acc[12], acc[13], acc[14], acc[15]);
}

// ---------------------------------------------------------------- reduce + tanh + g-split
__global__ __launch_bounds__(256, 2) void reduce_k(
    const float* __restrict__ wiu, const float* __restrict__ part, int nparts,
    const float* __restrict__ W, float* __restrict__ h,
    __nv_bfloat16* __restrict__ gThi, __nv_bfloat16* __restrict__ gTlo,
    float* __restrict__ outf, int col_off)
{
    __shared__ float Hs[32][65];
    __shared__ float Ws[64][68];
    const int tid = threadIdx.x;
    const int m0 = blockIdx.x * 32;

    if (!outf) {
        for (int i = tid; i < 4096; i += 256)
            Ws[i & 63][i >> 6] = W[i];
    }

    const int row = tid >> 3;
    const int c8 = (tid & 7) << 3;
    const int m = m0 + row;
    float z[8];
    {
        const float* wp = wiu + m * 64 + c8;
        float4 a = *(const float4*)(wp), b = *(const float4*)(wp + 4);
        z[0]=a.x; z[1]=a.y; z[2]=a.z; z[3]=a.w; z[4]=b.x; z[5]=b.y; z[6]=b.z; z[7]=b.w;
        for (int p = 0; p < nparts; ++p) {
            const float* pp = part + (size_t)p * (NN * 64) + m * 64 + c8;
            float4 c = *(const float4*)(pp), d = *(const float4*)(pp + 4);
            z[0]+=c.x; z[1]+=c.y; z[2]+=c.z; z[3]+=c.w;
            z[4]+=d.x; z[5]+=d.y; z[6]+=d.z; z[7]+=d.w;
        }
    }
#pragma unroll
    for (int j = 0; j < 8; ++j) z[j] = tanhf(z[j]);

    if (outf) {
        *(float4*)(h + m * 64 + c8)     = make_float4(z[0], z[1], z[2], z[3]);
        *(float4*)(h + m * 64 + c8 + 4) = make_float4(z[4], z[5], z[6], z[7]);
        float* op = outf + m * 128 + col_off + c8;
        *(float4*)(op)     = make_float4(z[0], z[1], z[2], z[3]);
        *(float4*)(op + 4) = make_float4(z[4], z[5], z[6], z[7]);
        return;
    }

#pragma unroll
    for (int j = 0; j < 8; ++j) Hs[row][c8 + j] = z[j];
    __syncthreads();

    const int r2 = tid & 31;
    const int cg2 = tid >> 5;
    float ga[8];
#pragma unroll
    for (int j = 0; j < 8; ++j) ga[j] = 0.f;
#pragma unroll 8
    for (int k = 0; k < 64; ++k) {
        float a = Hs[r2][k];
        const float* wr = &Ws[k][cg2 << 3];
        float4 w0 = *(const float4*)(wr + 0);
        float4 w1 = *(const float4*)(wr + 4);
        ga[0] = fmaf(a, w0.x, ga[0]); ga[1] = fmaf(a, w0.y, ga[1]);
        ga[2] = fmaf(a, w0.z, ga[2]); ga[3] = fmaf(a, w0.w, ga[3]);
        ga[4] = fmaf(a, w1.x, ga[4]); ga[5] = fmaf(a, w1.y, ga[5]);
        ga[6] = fmaf(a, w1.z, ga[6]); ga[7] = fmaf(a, w1.w, ga[7]);
    }
#pragma unroll
    for (int j = 0; j < 8; ++j) {
        float v = ga[j];
        __nv_bfloat16 hi = __float2bfloat16(v);
        __nv_bfloat16 lo = __float2bfloat16(v - __bfloat162float(hi));
        int col = (cg2 << 3) + j;
        gThi[col * NN + m0 + r2] = hi;
        gTlo[col * NN + m0 + r2] = lo;
    }
}

// ---------------------------------------------------------------- big HMMA GEMM
// part[ks][4096][64] = per-CTA K-split partial of L @ g (4-term split bf16)
// grid 128 = 32 M-tiles x 4 K-splits, block 512 (16 warps: 4 M-groups x 4 N-groups)
// 4 stages of 48KB: Ahi 16KB | Alo 16KB | Bhi 8KB | Blo 8KB  (SW128 rows of 128B)
#define STAGE_BYTES 49152
#define NSTAGE 4

__device__ __forceinline__ void load_stage(
    uint32_t st, int kbase, int m0, int tid,
    const __nv_bfloat16* __restrict__ Lhi, const __nv_bfloat16* __restrict__ Llo,
    const __nv_bfloat16* __restrict__ gThi, const __nv_bfloat16* __restrict__ gTlo)
{
#pragma unroll
    for (int r = 0; r < 2; ++r) {
        int o = tid + 512 * r;
        int row = o >> 3, seg = o & 7;
        uint32_t soff = SWZ128((uint32_t)(row * 128 + seg * 16));
        size_t goff = (size_t)(m0 + row) * NN + kbase + seg * 8;
        cp16(st + soff,         Lhi + goff);
        cp16(st + 16384 + soff, Llo + goff);
    }
    {
        int row = tid >> 3, seg = tid & 7;
        uint32_t soff = SWZ128((uint32_t)(row * 128 + seg * 16));
        size_t goff = (size_t)row * NN + kbase + seg * 8;
        cp16(st + 32768 + soff, gThi + goff);
        cp16(st + 40960 + soff, gTlo + goff);
    }
    CP_COMMIT();
}

__global__ __launch_bounds__(512, 1) void bigmma_k(
    const __nv_bfloat16* __restrict__ Lhi, const __nv_bfloat16* __restrict__ Llo,
    const __nv_bfloat16* __restrict__ gThi, const __nv_bfloat16* __restrict__ gTlo,
    float* __restrict__ part)
{
    extern __shared__ __align__(1024) char smem[];
    const uint32_t sb = smem_u32(smem);
    const int tid = threadIdx.x;
    const int wid = tid >> 5, lane = tid & 31;
    const int mtile = blockIdx.x >> 2, ks = blockIdx.x & 3;
    const int m0 = mtile * 128;
    const int kbase0 = ks * 1024;

    const int wm = wid >> 2;           // 0..3: m-range wm*32
    const int wn = wid & 3;            // 0..3: n-range wn*16

    // ldmatrix lane mapping: mat = lane/8 -> {rows0-7@k0, rows8-15@k0, rows0-7@k8, rows8-15@k8}
    const int lrow8 = (lane & 7) + ((lane >> 3) & 1) * 8;
    const int lk16  = (lane >> 4) * 16;

    uint32_t arow[2];
#pragma unroll
    for (int t = 0; t < 2; ++t)
        arow[t] = (uint32_t)(wm * 32 + t * 16 + lrow8) * 128;
    const uint32_t brow = (uint32_t)(wn * 16 + lrow8) * 128;

    float acc[2][2][4];
#pragma unroll
    for (int t = 0; t < 2; ++t)
#pragma unroll
        for (int g = 0; g < 2; ++g)
#pragma unroll
            for (int j = 0; j < 4; ++j) acc[t][g][j] = 0.f;

    // prologue: stages 0..3
#pragma unroll
    for (int c = 0; c < NSTAGE; ++c)
        load_stage(sb + c * STAGE_BYTES, kbase0 + c * 64, m0, tid,
                   Lhi, Llo, gThi, gTlo);

#pragma unroll 1
    for (int c = 0; c < 16; ++c) {
        CP_WAIT3();
        __syncthreads();

        const uint32_t st = sb + (c & 3) * STAGE_BYTES;
        const uint32_t stAhi = st, stAlo = st + 16384;
        const uint32_t stBhi = st + 32768, stBlo = st + 40960;

#pragma unroll
        for (int j = 0; j < 4; ++j) {
            const uint32_t kb = (uint32_t)(j * 32) + lk16;

            uint32_t bh[4], bl[4];
            ldsm_x4(bh, stBhi + SWZ128(brow + kb));
            ldsm_x4(bl, stBlo + SWZ128(brow + kb));

            uint32_t ah[2][4], al[2][4];
#pragma unroll
            for (int t = 0; t < 2; ++t) {
                ldsm_x4(ah[t], stAhi + SWZ128(arow[t] + kb));
                ldsm_x4(al[t], stAlo + SWZ128(arow[t] + kb));
            }

#pragma unroll
            for (int t = 0; t < 2; ++t) {
                // hi*hi
                mma16816(acc[t][0], ah[t], bh[0], bh[2]);
                mma16816(acc[t][1], ah[t], bh[1], bh[3]);
                // lo*hi
                mma16816(acc[t][0], al[t], bh[0], bh[2]);
                mma16816(acc[t][1], al[t], bh[1], bh[3]);
                // hi*lo
                mma16816(acc[t][0], ah[t], bl[0], bl[2]);
                mma16816(acc[t][1], ah[t], bl[1], bl[3]);
                // lo*lo
                mma16816(acc[t][0], al[t], bl[0], bl[2]);
                mma16816(acc[t][1], al[t], bl[1], bl[3]);
            }
        }
        __syncthreads();

        if (c + NSTAGE < 16)
            load_stage(st, kbase0 + (c + NSTAGE) * 64, m0, tid, Lhi, Llo, gThi, gTlo);
        else
            CP_COMMIT();   // keep wait_group accounting valid
    }

    // epilogue: write partial tile
    const int l4 = lane >> 2;
    const int l2 = (lane & 3) * 2;
    float* pbase = part + (size_t)ks * (NN * 64);
#pragma unroll
    for (int t = 0; t < 2; ++t) {
        int mrow = m0 + wm * 32 + t * 16 + l4;
        float* p0 = pbase + (size_t)mrow * 64 + wn * 16;
        float* p1 = p0 + 8 * 64;
        *(float2*)(p0 + l2)     = make_float2(acc[t][0][0], acc[t][0][1]);
        *(float2*)(p0 + 8 + l2) = make_float2(acc[t][1][0], acc[t][1][1]);
        *(float2*)(p1 + l2)     = make_float2(acc[t][0][2], acc[t][0][3]);
        *(float2*)(p1 + 8 + l2) = make_float2(acc[t][1][2], acc[t][1][3]);
    }
}

// ----------------------------------------------------------------
extern "C" void kernel_launch(void* const* d_in, const int* in_sizes, int n_in,
                              void* d_out, int out_size)
{
    const float* X    = (const float*)d_in[0];
    const float* L    = (const float*)d_in[1];
    const float* Wih0 = (const float*)d_in[2];
    const float* Whh0 = (const float*)d_in[3];
    const float* Wih1 = (const float*)d_in[4];
    const float* Whh1 = (const float*)d_in[5];
    float* out = (float*)d_out;

    float *wiu, *h, *part;
    __nv_bfloat16 *Lhi, *Llo, *gThi, *gTlo;
    cudaGetSymbolAddress((void**)&wiu,  d_wiu);
    cudaGetSymbolAddress((void**)&h,    d_h);
    cudaGetSymbolAddress((void**)&part, d_part);
    cudaGetSymbolAddress((void**)&Lhi,  d_Lhi);
    cudaGetSymbolAddress((void**)&Llo,  d_Llo);
    cudaGetSymbolAddress((void**)&gThi, d_gThi);
    cudaGetSymbolAddress((void**)&gTlo, d_gTlo);

    const int DYN_SMEM = NSTAGE * STAGE_BYTES;   // 196608
    cudaFuncSetAttribute(bigmma_k, cudaFuncAttributeMaxDynamicSharedMemorySize, DYN_SMEM);

    // one-time-per-launch: split L into bf16 hi/lo
    lsplit_k<<<(NN * NN) / (256 * 4), 256>>>(L, Lhi, Llo);

    for (int layer = 0; layer < 2; ++layer) {
        const float* Wih = layer ? Wih1 : Wih0;
        const float* Whh = layer ? Whh1 : Whh0;
        const float* Ain = layer ? h : X;

        small_gemm_k<<<64, 256>>>(Ain, Wih, wiu);
        // step 1: h = tanh(wiu), produce gT hi/lo
        reduce_k<<<128, 256>>>(wiu, part, 0, Whh, h, gThi, gTlo, nullptr, 0);

        // steps 2..10
        for (int it = 0; it < 9; ++it) {
            const int last = (it == 8);
            bigmma_k<<<128, 512, DYN_SMEM>>>(Lhi, Llo, gThi, gTlo, part);
            reduce_k<<<128, 256>>>(wiu, part, 4, Whh, h, gThi, gTlo,
                                   last ? out : nullptr, layer * 64);
        }
    }
}

// round 5
// speedup vs baseline: 1.1820x; 1.1820x over previous
#include <cuda_runtime.h>
#include <cuda_fp16.h>
#include <math.h>
#include <stdint.h>

#define NN 4096
#define HH 64
#define KSPLIT 8
#define LSCALE 256.0f
#define LDESCALE (1.0f / 256.0f)

// ---------------------------------------------------------------- scratch
__device__ float d_wiu[NN * HH];
__device__ float d_h[NN * HH];
__device__ float d_part[KSPLIT * NN * HH];
__device__ __half d_Lhi[(size_t)NN * NN];     // 256*L hi
__device__ __half d_Llo[(size_t)NN * NN];     // 256*L lo
__device__ __half d_gThi[HH * NN];            // g^T [64][4096]
__device__ __half d_gTlo[HH * NN];

// ---------------------------------------------------------------- PTX utils
__device__ __forceinline__ uint32_t smem_u32(const void* p) {
    uint32_t a;
    asm("{ .reg .u64 t; cvta.to.shared.u64 t, %1; cvt.u32.u64 %0, t; }"
        : "=r"(a) : "l"(p));
    return a;
}
#define SWZ128(o) ((o) ^ (((o) >> 3) & 0x70))

__device__ __forceinline__ void cp16(uint32_t s, const void* g) {
    asm volatile("cp.async.cg.shared.global [%0], [%1], 16;" :: "r"(s), "l"(g));
}
#define CP_COMMIT() asm volatile("cp.async.commit_group;" ::: "memory")
#define CP_WAIT1()  asm volatile("cp.async.wait_group 1;" ::: "memory")

__device__ __forceinline__ void ldsm_x4(uint32_t* r, uint32_t addr) {
    asm volatile("ldmatrix.sync.aligned.m8n8.x4.shared.b16 {%0,%1,%2,%3}, [%4];"
        : "=r"(r[0]), "=r"(r[1]), "=r"(r[2]), "=r"(r[3]) : "r"(addr));
}

__device__ __forceinline__ void mma16816(float* c, const uint32_t* a,
                                         uint32_t b0, uint32_t b1) {
    asm volatile(
        "mma.sync.aligned.m16n8k16.row.col.f32.f16.f16.f32 "
        "{%0,%1,%2,%3}, {%4,%5,%6,%7}, {%8,%9}, {%0,%1,%2,%3};"
        : "+f"(c[0]), "+f"(c[1]), "+f"(c[2]), "+f"(c[3])
        : "r"(a[0]), "r"(a[1]), "r"(a[2]), "r"(a[3]), "r"(b0), "r"(b1));
}

// ---------------------------------------------------------------- L split (once)
// Lhi/Llo hold 256*L split into fp16 hi + lo (lo stays in normal range).
__global__ __launch_bounds__(256, 4) void lsplit_k(
    const float* __restrict__ L,
    __half* __restrict__ Lhi, __half* __restrict__ Llo)
{
    size_t i = ((size_t)blockIdx.x * 256 + threadIdx.x) * 4;
    float4 v = *(const float4*)(L + i);
    float s0 = v.x * LSCALE, s1 = v.y * LSCALE, s2 = v.z * LSCALE, s3 = v.w * LSCALE;
    __half h0 = __float2half_rn(s0), h1 = __float2half_rn(s1);
    __half h2 = __float2half_rn(s2), h3 = __float2half_rn(s3);
    __half l0 = __float2half_rn(s0 - __half2float(h0));
    __half l1 = __float2half_rn(s1 - __half2float(h1));
    __half l2 = __float2half_rn(s2 - __half2float(h2));
    __half l3 = __float2half_rn(s3 - __half2float(h3));
    __half2 hp0 = __halves2half2(h0, h1), hp1 = __halves2half2(h2, h3);
    __half2 lp0 = __halves2half2(l0, l1), lp1 = __halves2half2(l2, l3);
    *(uint2*)(Lhi + i) = make_uint2(*(uint32_t*)&hp0, *(uint32_t*)&hp1);
    *(uint2*)(Llo + i) = make_uint2(*(uint32_t*)&lp0, *(uint32_t*)&lp1);
}

// ---------------------------------------------------------------- wiu small GEMM
__global__ __launch_bounds__(256, 1) void small_gemm_k(
    const float* __restrict__ A, const float* __restrict__ W,
    float* __restrict__ out)
{
    __shared__ float As[64][65];
    __shared__ float Ws[64][68];
    const int tid = threadIdx.x;
    const int base = blockIdx.x * (64 * 64);
    for (int i = tid; i < 4096; i += 256) {
        Ws[i & 63][i >> 6] = W[i];
        As[i >> 6][i & 63] = A[base + i];
    }
    __syncthreads();
    const int r = tid & 63, cg = tid >> 6;
    float acc[16];
#pragma unroll
    for (int j = 0; j < 16; ++j) acc[j] = 0.f;
#pragma unroll 8
    for (int k = 0; k < 64; ++k) {
        float a = As[r][k];
        const float* wr = &Ws[k][cg << 4];
        float4 b0 = *(const float4*)(wr + 0);
        float4 b1 = *(const float4*)(wr + 4);
        float4 b2 = *(const float4*)(wr + 8);
        float4 b3 = *(const float4*)(wr + 12);
        acc[0]  = fmaf(a, b0.x, acc[0]);  acc[1]  = fmaf(a, b0.y, acc[1]);
        acc[2]  = fmaf(a, b0.z, acc[2]);  acc[3]  = fmaf(a, b0.w, acc[3]);
        acc[4]  = fmaf(a, b1.x, acc[4]);  acc[5]  = fmaf(a, b1.y, acc[5]);
        acc[6]  = fmaf(a, b1.z, acc[6]);  acc[7]  = fmaf(a, b1.w, acc[7]);
        acc[8]  = fmaf(a, b2.x, acc[8]);  acc[9]  = fmaf(a, b2.y, acc[9]);
        acc[10] = fmaf(a, b2.z, acc[10]); acc[11] = fmaf(a, b2.w, acc[11]);
        acc[12] = fmaf(a, b3.x, acc[12]); acc[13] = fmaf(a, b3.y, acc[13]);
        acc[14] = fmaf(a, b3.z, acc[14]); acc[15] = fmaf(a, b3.w, acc[15]);
    }
    float* op = out + base + r * 64 + (cg << 4);
    *(float4*)(op + 0)  = make_float4(acc[0],  acc[1],  acc[2],  acc[3]);
    *(float4*)(op + 4)  = make_float4(acc[4],  acc[5],  acc[6],  acc[7]);
    *(float4*)(op + 8)  = make_float4(acc[8],  acc[9],  acc[10], acc[11]);
    *(float4*)(op + 12) = make_float4(acc[12], acc[13], acc[14], acc[15]);
}

// ---------------------------------------------------------------- reduce + tanh + g-split
__global__ __launch_bounds__(256, 2) void reduce_k(
    const float* __restrict__ wiu, const float* __restrict__ part, int nparts,
    const float* __restrict__ W, float* __restrict__ h,
    __half* __restrict__ gThi, __half* __restrict__ gTlo,
    float* __restrict__ outf, int col_off)
{
    __shared__ float Hs[32][65];
    __shared__ float Ws[64][68];
    const int tid = threadIdx.x;
    const int m0 = blockIdx.x * 32;

    if (!outf) {
        for (int i = tid; i < 4096; i += 256)
            Ws[i & 63][i >> 6] = W[i];
    }

    const int row = tid >> 3;
    const int c8 = (tid & 7) << 3;
    const int m = m0 + row;
    float z[8];
    {
        float s[8];
#pragma unroll
        for (int j = 0; j < 8; ++j) s[j] = 0.f;
        for (int p = 0; p < nparts; ++p) {
            const float* pp = part + (size_t)p * (NN * 64) + m * 64 + c8;
            float4 c = *(const float4*)(pp), d = *(const float4*)(pp + 4);
            s[0]+=c.x; s[1]+=c.y; s[2]+=c.z; s[3]+=c.w;
            s[4]+=d.x; s[5]+=d.y; s[6]+=d.z; s[7]+=d.w;
        }
        const float* wp = wiu + m * 64 + c8;
        float4 a = *(const float4*)(wp), b = *(const float4*)(wp + 4);
        z[0] = a.x + s[0]*LDESCALE; z[1] = a.y + s[1]*LDESCALE;
        z[2] = a.z + s[2]*LDESCALE; z[3] = a.w + s[3]*LDESCALE;
        z[4] = b.x + s[4]*LDESCALE; z[5] = b.y + s[5]*LDESCALE;
        z[6] = b.z + s[6]*LDESCALE; z[7] = b.w + s[7]*LDESCALE;
    }
#pragma unroll
    for (int j = 0; j < 8; ++j) z[j] = tanhf(z[j]);

    if (outf) {
        *(float4*)(h + m * 64 + c8)     = make_float4(z[0], z[1], z[2], z[3]);
        *(float4*)(h + m * 64 + c8 + 4) = make_float4(z[4], z[5], z[6], z[7]);
        float* op = outf + m * 128 + col_off + c8;
        *(float4*)(op)     = make_float4(z[0], z[1], z[2], z[3]);
        *(float4*)(op + 4) = make_float4(z[4], z[5], z[6], z[7]);
        return;
    }

#pragma unroll
    for (int j = 0; j < 8; ++j) Hs[row][c8 + j] = z[j];
    __syncthreads();

    const int r2 = tid & 31;
    const int cg2 = tid >> 5;
    float ga[8];
#pragma unroll
    for (int j = 0; j < 8; ++j) ga[j] = 0.f;
#pragma unroll 8
    for (int k = 0; k < 64; ++k) {
        float a = Hs[r2][k];
        const float* wr = &Ws[k][cg2 << 3];
        float4 w0 = *(const float4*)(wr + 0);
        float4 w1 = *(const float4*)(wr + 4);
        ga[0] = fmaf(a, w0.x, ga[0]); ga[1] = fmaf(a, w0.y, ga[1]);
        ga[2] = fmaf(a, w0.z, ga[2]); ga[3] = fmaf(a, w0.w, ga[3]);
        ga[4] = fmaf(a, w1.x, ga[4]); ga[5] = fmaf(a, w1.y, ga[5]);
        ga[6] = fmaf(a, w1.z, ga[6]); ga[7] = fmaf(a, w1.w, ga[7]);
    }
#pragma unroll
    for (int j = 0; j < 8; ++j) {
        float v = ga[j];
        __half hi = __float2half_rn(v);
        __half lo = __float2half_rn(v - __half2float(hi));
        int col = (cg2 << 3) + j;
        gThi[col * NN + m0 + r2] = hi;
        gTlo[col * NN + m0 + r2] = lo;
    }
}

// ---------------------------------------------------------------- big HMMA GEMM
// part[ks][4096][64] = K-split partial of (256*L) @ g, 3-term fp16 split
// grid 256 = 32 M-tiles x 8 K-splits; block 256 (8 warps: 2m x 4n, warp m64n16)
// 2 stages x 48KB -> 96KB/CTA -> 2 CTAs/SM
#define STAGE_BYTES 49152
#define NSTAGE 2
#define NCHUNK 8

__device__ __forceinline__ void load_stage(
    uint32_t st, int kbase, int m0, int tid,
    const __half* __restrict__ Lhi, const __half* __restrict__ Llo,
    const __half* __restrict__ gThi, const __half* __restrict__ gTlo)
{
#pragma unroll
    for (int r = 0; r < 4; ++r) {
        int o = tid + 256 * r;
        int row = o >> 3, seg = o & 7;
        uint32_t soff = SWZ128((uint32_t)(row * 128 + seg * 16));
        size_t goff = (size_t)(m0 + row) * NN + kbase + seg * 8;
        cp16(st + soff,         Lhi + goff);
        cp16(st + 16384 + soff, Llo + goff);
    }
#pragma unroll
    for (int r = 0; r < 2; ++r) {
        int o = tid + 256 * r;
        int row = o >> 3, seg = o & 7;
        uint32_t soff = SWZ128((uint32_t)(row * 128 + seg * 16));
        size_t goff = (size_t)row * NN + kbase + seg * 8;
        cp16(st + 32768 + soff, gThi + goff);
        cp16(st + 40960 + soff, gTlo + goff);
    }
    CP_COMMIT();
}

__global__ __launch_bounds__(256, 2) void bigmma_k(
    const __half* __restrict__ Lhi, const __half* __restrict__ Llo,
    const __half* __restrict__ gThi, const __half* __restrict__ gTlo,
    float* __restrict__ part)
{
    extern __shared__ __align__(1024) char smem[];
    const uint32_t sb = smem_u32(smem);
    const int tid = threadIdx.x;
    const int wid = tid >> 5, lane = tid & 31;
    const int mtile = blockIdx.x >> 3, ks = blockIdx.x & 7;
    const int m0 = mtile * 128;
    const int kbase0 = ks * 512;

    const int wm = wid >> 2;           // 0/1: m-range wm*64
    const int wn = wid & 3;            // n-range wn*16

    const int lrow8 = (lane & 7) + ((lane >> 3) & 1) * 8;
    const int lk16  = (lane >> 4) * 16;

    uint32_t arow[4];
#pragma unroll
    for (int t = 0; t < 4; ++t)
        arow[t] = (uint32_t)(wm * 64 + t * 16 + lrow8) * 128;
    const uint32_t brow = (uint32_t)(wn * 16 + lrow8) * 128;

    float acc[4][2][4];
#pragma unroll
    for (int t = 0; t < 4; ++t)
#pragma unroll
        for (int g = 0; g < 2; ++g)
#pragma unroll
            for (int j = 0; j < 4; ++j) acc[t][g][j] = 0.f;

    // prologue: chunks 0,1
#pragma unroll
    for (int c = 0; c < NSTAGE; ++c)
        load_stage(sb + c * STAGE_BYTES, kbase0 + c * 64, m0, tid,
                   Lhi, Llo, gThi, gTlo);

#pragma unroll 1
    for (int c = 0; c < NCHUNK; ++c) {
        CP_WAIT1();
        __syncthreads();

        const uint32_t st = sb + (c & 1) * STAGE_BYTES;
        const uint32_t stAhi = st, stAlo = st + 16384;
        const uint32_t stBhi = st + 32768, stBlo = st + 40960;

#pragma unroll
        for (int j = 0; j < 4; ++j) {
            const uint32_t kb = (uint32_t)(j * 32) + lk16;

            uint32_t bh[4], bl[4];
            ldsm_x4(bh, stBhi + SWZ128(brow + kb));
            ldsm_x4(bl, stBlo + SWZ128(brow + kb));

            uint32_t ah[4][4], al[4][4];
#pragma unroll
            for (int t = 0; t < 4; ++t) {
                ldsm_x4(ah[t], stAhi + SWZ128(arow[t] + kb));
                ldsm_x4(al[t], stAlo + SWZ128(arow[t] + kb));
            }

#pragma unroll
            for (int t = 0; t < 4; ++t) {
                mma16816(acc[t][0], ah[t], bh[0], bh[2]);
                mma16816(acc[t][1], ah[t], bh[1], bh[3]);
                mma16816(acc[t][0], al[t], bh[0], bh[2]);
                mma16816(acc[t][1], al[t], bh[1], bh[3]);
                mma16816(acc[t][0], ah[t], bl[0], bl[2]);
                mma16816(acc[t][1], ah[t], bl[1], bl[3]);
            }
        }
        __syncthreads();

        if (c + NSTAGE < NCHUNK)
            load_stage(st, kbase0 + (c + NSTAGE) * 64, m0, tid,
                       Lhi, Llo, gThi, gTlo);
        else
            CP_COMMIT();   // keep wait_group accounting valid
    }

    // epilogue: write partial tile
    const int l4 = lane >> 2;
    const int l2 = (lane & 3) * 2;
    float* pbase = part + (size_t)ks * (NN * 64);
#pragma unroll
    for (int t = 0; t < 4; ++t) {
        int mrow = m0 + wm * 64 + t * 16 + l4;
        float* p0 = pbase + (size_t)mrow * 64 + wn * 16;
        float* p1 = p0 + 8 * 64;
        *(float2*)(p0 + l2)     = make_float2(acc[t][0][0], acc[t][0][1]);
        *(float2*)(p0 + 8 + l2) = make_float2(acc[t][1][0], acc[t][1][1]);
        *(float2*)(p1 + l2)     = make_float2(acc[t][0][2], acc[t][0][3]);
        *(float2*)(p1 + 8 + l2) = make_float2(acc[t][1][2], acc[t][1][3]);
    }
}

// ----------------------------------------------------------------
extern "C" void kernel_launch(void* const* d_in, const int* in_sizes, int n_in,
                              void* d_out, int out_size)
{
    const float* X    = (const float*)d_in[0];
    const float* L    = (const float*)d_in[1];
    const float* Wih0 = (const float*)d_in[2];
    const float* Whh0 = (const float*)d_in[3];
    const float* Wih1 = (const float*)d_in[4];
    const float* Whh1 = (const float*)d_in[5];
    float* out = (float*)d_out;

    float *wiu, *h, *part;
    __half *Lhi, *Llo, *gThi, *gTlo;
    cudaGetSymbolAddress((void**)&wiu,  d_wiu);
    cudaGetSymbolAddress((void**)&h,    d_h);
    cudaGetSymbolAddress((void**)&part, d_part);
    cudaGetSymbolAddress((void**)&Lhi,  d_Lhi);
    cudaGetSymbolAddress((void**)&Llo,  d_Llo);
    cudaGetSymbolAddress((void**)&gThi, d_gThi);
    cudaGetSymbolAddress((void**)&gTlo, d_gTlo);

    const int DYN_SMEM = NSTAGE * STAGE_BYTES;   // 98304 -> 2 CTAs/SM
    cudaFuncSetAttribute(bigmma_k, cudaFuncAttributeMaxDynamicSharedMemorySize, DYN_SMEM);

    // one-time-per-launch: split 256*L into fp16 hi/lo
    lsplit_k<<<(NN * NN) / (256 * 4), 256>>>(L, Lhi, Llo);

    for (int layer = 0; layer < 2; ++layer) {
        const float* Wih = layer ? Wih1 : Wih0;
        const float* Whh = layer ? Whh1 : Whh0;
        const float* Ain = layer ? h : X;

        small_gemm_k<<<64, 256>>>(Ain, Wih, wiu);
        // step 1: h = tanh(wiu), produce gT hi/lo
        reduce_k<<<128, 256>>>(wiu, part, 0, Whh, h, gThi, gTlo, nullptr, 0);

        // steps 2..10
        for (int it = 0; it < 9; ++it) {
            const int last = (it == 8);
            bigmma_k<<<256, 256, DYN_SMEM>>>(Lhi, Llo, gThi, gTlo, part);
            reduce_k<<<128, 256>>>(wiu, part, KSPLIT, Whh, h, gThi, gTlo,
                                   last ? out : nullptr, layer * 64);
        }
    }
}